// round 3
// baseline (speedup 1.0000x reference)
#include <cuda_runtime.h>
#include <cuda_bf16.h>
#include <math.h>

#define NN 100000
#define EE 1600000
#define F_IN 1433
#define DD 64
#define DEPTH 3
#define ALPHA 0.9f
#define KC_EMB 90   // ceil(1433/16)

// ---------------- scratch (static device globals) ----------------
__device__ float g_x0[NN * DD];
__device__ float g_x [NN * DD];
__device__ float g_h [NN * DD];   // LN output, later reused as agg
__device__ float g_q [NN * DD];
__device__ float g_k [NN * DD];
__device__ float g_v [NN * DD];
__device__ float g_o [NN * DD];
__device__ int   g_deg[NN];
__device__ int   g_off[NN + 1];
__device__ int   g_pos[NN];
__device__ int   g_csr[EE];
__device__ uint4 g_Bemb[KC_EMB * 256];   // packed split-bf16 emb weight
__device__ uint4 g_Bw[12 * 1024];        // q,k,v,o x 3 layers (K=64 -> KC=4)

// ---------------- helpers ----------------
__device__ __forceinline__ void split2(float x, float y, unsigned& hi, unsigned& lo) {
    __nv_bfloat162 h = __floats2bfloat162_rn(x, y);
    float rx = x - __low2float(h);
    float ry = y - __high2float(h);
    __nv_bfloat162 l = __floats2bfloat162_rn(rx, ry);
    hi = *reinterpret_cast<unsigned*>(&h);
    lo = *reinterpret_cast<unsigned*>(&l);
}

__device__ __forceinline__ void mma16816(float* c, const unsigned* a,
                                         unsigned b0, unsigned b1) {
    asm volatile(
        "mma.sync.aligned.m16n8k16.row.col.f32.bf16.bf16.f32 "
        "{%0,%1,%2,%3},{%4,%5,%6,%7},{%8,%9},{%0,%1,%2,%3};\n"
        : "+f"(c[0]), "+f"(c[1]), "+f"(c[2]), "+f"(c[3])
        : "r"(a[0]), "r"(a[1]), "r"(a[2]), "r"(a[3]), "r"(b0), "r"(b1));
}

// ---------------- B packing ----------------
__global__ void pack_b_kernel(const float* __restrict__ B, uint4* __restrict__ out,
                              int K, int KC) {
    int idx = blockIdx.x * blockDim.x + threadIdx.x;
    if (idx >= KC * 256) return;
    int lane = idx & 31, nt = (idx >> 5) & 7, kc = idx >> 8;
    int col = nt * 8 + (lane >> 2);
    int kr = kc * 16 + (lane & 3) * 2;
    float f0 = (kr     < K) ? B[(kr    ) * 64 + col] : 0.f;
    float f1 = (kr + 1 < K) ? B[(kr + 1) * 64 + col] : 0.f;
    float f2 = (kr + 8 < K) ? B[(kr + 8) * 64 + col] : 0.f;
    float f3 = (kr + 9 < K) ? B[(kr + 9) * 64 + col] : 0.f;
    unsigned h0, l0, h1, l1;
    split2(f0, f1, h0, l0);
    split2(f2, f3, h1, l1);
    out[idx] = make_uint4(h0, h1, l0, l1);
}

__global__ void pack_w_kernel(const float* __restrict__ Wq, const float* __restrict__ Wk,
                              const float* __restrict__ Wv, const float* __restrict__ Wo,
                              uint4* __restrict__ out) {
    int idx = blockIdx.x * blockDim.x + threadIdx.x;
    if (idx >= 12 * 1024) return;
    int m = idx >> 10;
    int l = m >> 2, w = m & 3;
    const float* B = (w == 0 ? Wq : w == 1 ? Wk : w == 2 ? Wv : Wo) + l * 4096;
    int rest = idx & 1023;
    int lane = rest & 31, nt = (rest >> 5) & 7, kc = rest >> 8;
    int col = nt * 8 + (lane >> 2);
    int kr = kc * 16 + (lane & 3) * 2;
    float f0 = B[(kr    ) * 64 + col];
    float f1 = B[(kr + 1) * 64 + col];
    float f2 = B[(kr + 8) * 64 + col];
    float f3 = B[(kr + 9) * 64 + col];
    unsigned h0, l0, h1, l1;
    split2(f0, f1, h0, l0);
    split2(f2, f3, h1, l1);
    out[idx] = make_uint4(h0, h1, l0, l1);
}

// ---------------- split-bf16 tensor-core GEMM ----------------
// C[m][M x 64] = A[M x K] @ B_m[K x 64], NB output matrices, MR 16-row
// fragments per warp. block = 128 thr (4 warps).
__device__ __forceinline__ float ldA(const float* __restrict__ A, long off, int c,
                                     int K, bool rok) {
    return (rok && c < K) ? __ldg(A + off + c) : 0.f;
}

template <int NB, int MR>
__global__ __launch_bounds__(128)
void mma_gemm_kernel(const float* __restrict__ A, const uint4* __restrict__ Bp,
                     float* __restrict__ O0, float* __restrict__ O1,
                     float* __restrict__ O2,
                     const float* __restrict__ bias, int M, int K, int KC) {
    const int warp = threadIdx.x >> 5, lane = threadIdx.x & 31;
    const int rw = blockIdx.x * (64 * MR) + warp * (16 * MR) + (lane >> 2);
    bool rok[2 * MR];
    long offs[2 * MR];
#pragma unroll
    for (int f = 0; f < MR; ++f) {
        rok[2 * f]     = (rw + f * 16)     < M;
        rok[2 * f + 1] = (rw + f * 16 + 8) < M;
        offs[2 * f]     = (long)(rw + f * 16)     * K;
        offs[2 * f + 1] = (long)(rw + f * 16 + 8) * K;
    }

    float acc[NB][MR][8][4];
#pragma unroll
    for (int m = 0; m < NB; ++m)
#pragma unroll
        for (int f = 0; f < MR; ++f)
#pragma unroll
            for (int nt = 0; nt < 8; ++nt)
#pragma unroll
                for (int j = 0; j < 4; ++j) acc[m][f][nt][j] = 0.f;

    for (int kc = 0; kc < KC; ++kc) {
        int c0 = kc * 16 + (lane & 3) * 2;
        unsigned ahi[MR][4], alo[MR][4];
#pragma unroll
        for (int f = 0; f < MR; ++f) {
            float f0 = ldA(A, offs[2*f],   c0,     K, rok[2*f]);
            float f1 = ldA(A, offs[2*f],   c0 + 1, K, rok[2*f]);
            float f2 = ldA(A, offs[2*f+1], c0,     K, rok[2*f+1]);
            float f3 = ldA(A, offs[2*f+1], c0 + 1, K, rok[2*f+1]);
            float f4 = ldA(A, offs[2*f],   c0 + 8, K, rok[2*f]);
            float f5 = ldA(A, offs[2*f],   c0 + 9, K, rok[2*f]);
            float f6 = ldA(A, offs[2*f+1], c0 + 8, K, rok[2*f+1]);
            float f7 = ldA(A, offs[2*f+1], c0 + 9, K, rok[2*f+1]);
            split2(f0, f1, ahi[f][0], alo[f][0]);
            split2(f2, f3, ahi[f][1], alo[f][1]);
            split2(f4, f5, ahi[f][2], alo[f][2]);
            split2(f6, f7, ahi[f][3], alo[f][3]);
        }
        const uint4* bp = Bp + (size_t)kc * 256 + lane;
#pragma unroll
        for (int m = 0; m < NB; ++m) {
            const uint4* bm = bp + (size_t)m * KC * 256;
#pragma unroll
            for (int nt = 0; nt < 8; ++nt) {
                uint4 b = __ldg(&bm[nt * 32]);
#pragma unroll
                for (int f = 0; f < MR; ++f) {
                    mma16816(acc[m][f][nt], ahi[f], b.x, b.y);  // hi*hi
                    mma16816(acc[m][f][nt], alo[f], b.x, b.y);  // lo*hi
                    mma16816(acc[m][f][nt], ahi[f], b.z, b.w);  // hi*lo
                }
            }
        }
    }

    float* outs[3];
    outs[0] = O0; outs[1] = O1; outs[2] = O2;
#pragma unroll
    for (int m = 0; m < NB; ++m) {
        float* O = outs[m];
#pragma unroll
        for (int f = 0; f < MR; ++f)
#pragma unroll
            for (int nt = 0; nt < 8; ++nt) {
                int cc = nt * 8 + (lane & 3) * 2;
                float b0 = bias ? bias[cc] : 0.f;
                float b1 = bias ? bias[cc + 1] : 0.f;
                if (rok[2*f])
                    *(float2*)(O + (long)(rw + f*16) * 64 + cc) =
                        make_float2(acc[m][f][nt][0] + b0, acc[m][f][nt][1] + b1);
                if (rok[2*f+1])
                    *(float2*)(O + (long)(rw + f*16 + 8) * 64 + cc) =
                        make_float2(acc[m][f][nt][2] + b0, acc[m][f][nt][3] + b1);
            }
    }
}

// ---------------- CSR construction ----------------
__global__ void zero_deg_kernel() {
    int i = blockIdx.x * blockDim.x + threadIdx.x;
    if (i < NN / 4) ((int4*)g_deg)[i] = make_int4(0, 0, 0, 0);
}

__global__ void hist_kernel(const int* __restrict__ ei) {
    int i = blockIdx.x * blockDim.x + threadIdx.x;
    if (i < EE / 4) {
        int4 d = ((const int4*)(ei + EE))[i];
        atomicAdd(&g_deg[d.x], 1);
        atomicAdd(&g_deg[d.y], 1);
        atomicAdd(&g_deg[d.z], 1);
        atomicAdd(&g_deg[d.w], 1);
    }
}

__global__ void scan_kernel() {
    __shared__ int ssum[1024];
    const int t = threadIdx.x;
    const int CHUNK = (NN + 1023) / 1024;
    int beg = t * CHUNK;
    int end = beg + CHUNK; if (end > NN) end = NN;
    int s = 0;
    for (int i = beg; i < end; ++i) s += g_deg[i];
    ssum[t] = s;
    __syncthreads();
    for (int d = 1; d < 1024; d <<= 1) {
        int v = (t >= d) ? ssum[t - d] : 0;
        __syncthreads();
        ssum[t] += v;
        __syncthreads();
    }
    int run = (t == 0) ? 0 : ssum[t - 1];
    for (int i = beg; i < end; ++i) {
        g_off[i] = run;
        g_pos[i] = run;
        run += g_deg[i];
    }
    if (t == 1023) g_off[NN] = ssum[1023];
}

__global__ void fill_kernel(const int* __restrict__ ei) {
    int i = blockIdx.x * blockDim.x + threadIdx.x;
    if (i < EE / 4) {
        int4 s = ((const int4*)ei)[i];
        int4 d = ((const int4*)(ei + EE))[i];
        g_csr[atomicAdd(&g_pos[d.x], 1)] = s.x;
        g_csr[atomicAdd(&g_pos[d.y], 1)] = s.y;
        g_csr[atomicAdd(&g_pos[d.z], 1)] = s.z;
        g_csr[atomicAdd(&g_pos[d.w], 1)] = s.w;
    }
}

// ---------------- layer norm (standalone, layer 0 only) ----------------
__global__ void ln_kernel(const float* __restrict__ src,
                          const float* __restrict__ scale,
                          const float* __restrict__ bias) {
    int warp = (blockIdx.x * blockDim.x + threadIdx.x) >> 5;
    int lane = threadIdx.x & 31;
    if (warp >= NN) return;
    const float* xr = src + (size_t)warp * 64;
    float x0v = xr[lane], x1v = xr[lane + 32];
    float s = x0v + x1v;
    float sq = x0v * x0v + x1v * x1v;
#pragma unroll
    for (int o = 16; o; o >>= 1) {
        s  += __shfl_xor_sync(~0u, s,  o);
        sq += __shfl_xor_sync(~0u, sq, o);
    }
    float mu = s * (1.f / 64.f);
    float var = sq * (1.f / 64.f) - mu * mu;
    float rstd = rsqrtf(var + 1e-5f);
    float* hr = g_h + (size_t)warp * 64;
    hr[lane]      = (x0v - mu) * rstd * scale[lane]      + bias[lane];
    hr[lane + 32] = (x1v - mu) * rstd * scale[lane + 32] + bias[lane + 32];
}

// ---------------- fused edge attention: warp per dst, no-max softmax --------
__global__ __launch_bounds__(256)
void attn_kernel() {
    int warp = (blockIdx.x * blockDim.x + threadIdx.x) >> 5;
    int lane = threadIdx.x & 31;
    if (warp >= NN) return;
    const float* qr = g_q + (size_t)warp * 64;
    float q0 = qr[lane] * 0.25f, q1 = qr[lane + 32] * 0.25f;  // fold DH^-0.5
    float l0 = 0.f, l1 = 0.f, a0 = 0.f, a1 = 0.f;
    float l0b = 0.f, l1b = 0.f, a0b = 0.f, a1b = 0.f;
    int beg = g_off[warp], end = g_off[warp + 1];
    int e = beg;
    for (; e + 1 < end; e += 2) {
        int s0 = g_csr[e], s1 = g_csr[e + 1];
        const float* k0p = g_k + (size_t)s0 * 64;
        const float* v0p = g_v + (size_t)s0 * 64;
        const float* k1p = g_k + (size_t)s1 * 64;
        const float* v1p = g_v + (size_t)s1 * 64;
        float dA0 = q0 * k0p[lane], dA1 = q1 * k0p[lane + 32];
        float dB0 = q0 * k1p[lane], dB1 = q1 * k1p[lane + 32];
        float vA0 = v0p[lane], vA1 = v0p[lane + 32];
        float vB0 = v1p[lane], vB1 = v1p[lane + 32];
#pragma unroll
        for (int o = 8; o; o >>= 1) {
            dA0 += __shfl_xor_sync(~0u, dA0, o);
            dA1 += __shfl_xor_sync(~0u, dA1, o);
            dB0 += __shfl_xor_sync(~0u, dB0, o);
            dB1 += __shfl_xor_sync(~0u, dB1, o);
        }
        float pA0 = __expf(dA0), pA1 = __expf(dA1);
        float pB0 = __expf(dB0), pB1 = __expf(dB1);
        l0  += pA0;        l1  += pA1;
        a0  += pA0 * vA0;  a1  += pA1 * vA1;
        l0b += pB0;        l1b += pB1;
        a0b += pB0 * vB0;  a1b += pB1 * vB1;
    }
    if (e < end) {
        int s0 = g_csr[e];
        const float* k0p = g_k + (size_t)s0 * 64;
        const float* v0p = g_v + (size_t)s0 * 64;
        float dA0 = q0 * k0p[lane], dA1 = q1 * k0p[lane + 32];
        float vA0 = v0p[lane], vA1 = v0p[lane + 32];
#pragma unroll
        for (int o = 8; o; o >>= 1) {
            dA0 += __shfl_xor_sync(~0u, dA0, o);
            dA1 += __shfl_xor_sync(~0u, dA1, o);
        }
        float pA0 = __expf(dA0), pA1 = __expf(dA1);
        l0 += pA0; l1 += pA1; a0 += pA0 * vA0; a1 += pA1 * vA1;
    }
    l0 += l0b; l1 += l1b; a0 += a0b; a1 += a1b;
    float* ag = g_h + (size_t)warp * 64;
    ag[lane]      = a0 / (l0 + 1e-9f);
    ag[lane + 32] = a1 / (l1 + 1e-9f);
}

// ---------------- gated residual + alpha mix (+ fused next-layer LN) -------
__global__ void gate_kernel(const float* __restrict__ gw,
                            const float* __restrict__ gbp,
                            const float* __restrict__ res,
                            const float* __restrict__ x0,
                            float* __restrict__ dst,
                            const float* __restrict__ lns,
                            const float* __restrict__ lnb) {
    int warp = (blockIdx.x * blockDim.x + threadIdx.x) >> 5;
    int lane = threadIdx.x & 31;
    if (warp >= NN) return;
    size_t base = (size_t)warp * 64;
    float o0 = g_o[base + lane], o1 = g_o[base + lane + 32];
    float r0 = res[base + lane], r1 = res[base + lane + 32];
    float z0 = x0[base + lane],  z1 = x0[base + lane + 32];
    float s = o0 * gw[lane]        + o1 * gw[lane + 32]
            + r0 * gw[64 + lane]   + r1 * gw[96 + lane]
            + (o0 - r0) * gw[128 + lane] + (o1 - r1) * gw[160 + lane];
#pragma unroll
    for (int o = 16; o; o >>= 1) s += __shfl_xor_sync(~0u, s, o);
    float g = 1.f / (1.f + __expf(-(s + gbp[0])));
    float n0 = ALPHA * (g * o0 + (1.f - g) * r0) + (1.f - ALPHA) * z0;
    float n1 = ALPHA * (g * o1 + (1.f - g) * r1) + (1.f - ALPHA) * z1;
    dst[base + lane]      = n0;
    dst[base + lane + 32] = n1;
    if (lns) {  // fused LN for next layer -> g_h
        float sm = n0 + n1, sq = n0 * n0 + n1 * n1;
#pragma unroll
        for (int o = 16; o; o >>= 1) {
            sm += __shfl_xor_sync(~0u, sm, o);
            sq += __shfl_xor_sync(~0u, sq, o);
        }
        float mu = sm * (1.f / 64.f);
        float var = sq * (1.f / 64.f) - mu * mu;
        float rstd = rsqrtf(var + 1e-5f);
        g_h[base + lane]      = (n0 - mu) * rstd * lns[lane]      + lnb[lane];
        g_h[base + lane + 32] = (n1 - mu) * rstd * lns[lane + 32] + lnb[lane + 32];
    }
}

// ---------------- launch ----------------
extern "C" void kernel_launch(void* const* d_in, const int* in_sizes, int n_in,
                              void* d_out, int out_size) {
    const float* nodes = (const float*)d_in[0];
    const int*   ei    = (const int*)  d_in[1];
    const float* emb_W = (const float*)d_in[2];
    const float* emb_b = (const float*)d_in[3];
    const float* ln_s  = (const float*)d_in[4];
    const float* ln_b  = (const float*)d_in[5];
    const float* Wq    = (const float*)d_in[6];
    const float* Wk    = (const float*)d_in[7];
    const float* Wv    = (const float*)d_in[8];
    const float* Wo    = (const float*)d_in[9];
    const float* gW    = (const float*)d_in[10];
    const float* gb    = (const float*)d_in[11];
    float* out = (float*)d_out;

    float *px0, *px, *ph, *pq, *pk, *pv, *po;
    uint4 *pBemb, *pBw;
    cudaGetSymbolAddress((void**)&px0, g_x0);
    cudaGetSymbolAddress((void**)&px,  g_x);
    cudaGetSymbolAddress((void**)&ph,  g_h);
    cudaGetSymbolAddress((void**)&pq,  g_q);
    cudaGetSymbolAddress((void**)&pk,  g_k);
    cudaGetSymbolAddress((void**)&pv,  g_v);
    cudaGetSymbolAddress((void**)&po,  g_o);
    cudaGetSymbolAddress((void**)&pBemb, g_Bemb);
    cudaGetSymbolAddress((void**)&pBw,   g_Bw);

    // weight packing
    pack_b_kernel<<<(KC_EMB * 256 + 255) / 256, 256>>>(emb_W, pBemb, F_IN, KC_EMB);
    pack_w_kernel<<<(12 * 1024 + 255) / 256, 256>>>(Wq, Wk, Wv, Wo, pBw);

    // CSR build
    zero_deg_kernel<<<(NN / 4 + 255) / 256, 256>>>();
    hist_kernel<<<(EE / 4 + 255) / 256, 256>>>(ei);
    scan_kernel<<<1, 1024>>>();
    fill_kernel<<<(EE / 4 + 255) / 256, 256>>>(ei);

    // embedding: x0 = nodes @ emb_W + emb_b   (MR=2: 128 rows per block)
    mma_gemm_kernel<1, 2><<<(NN + 127) / 128, 128>>>(
        nodes, pBemb, px0, nullptr, nullptr, emb_b, NN, F_IN, KC_EMB);

    const int warpGrid = (NN + 7) / 8;
    const int gemmGrid = (NN + 63) / 64;
    // layer 0 LN reads x0 directly (x == x0 initially)
    ln_kernel<<<warpGrid, 256>>>(px0, ln_s, ln_b);
    for (int l = 0; l < DEPTH; ++l) {
        mma_gemm_kernel<3, 1><<<gemmGrid, 128>>>(
            ph, pBw + (size_t)(l * 4) * 1024, pq, pk, pv, nullptr, NN, 64, 4);
        attn_kernel<<<warpGrid, 256>>>();   // agg -> g_h
        mma_gemm_kernel<1, 1><<<gemmGrid, 128>>>(
            ph, pBw + (size_t)(l * 4 + 3) * 1024, po, nullptr, nullptr,
            nullptr, NN, 64, 4);
        const float* res = (l == 0) ? px0 : px;
        float* dst = (l == DEPTH - 1) ? out : px;
        const float* nls = (l == DEPTH - 1) ? nullptr : ln_s + (l + 1) * 64;
        const float* nlb = (l == DEPTH - 1) ? nullptr : ln_b + (l + 1) * 64;
        gate_kernel<<<warpGrid, 256>>>(gW + l * 192, gb + l, res, px0, dst,
                                       nls, nlb);
    }
}

// round 4
// speedup vs baseline: 1.1445x; 1.1445x over previous
#include <cuda_runtime.h>
#include <cuda_bf16.h>
#include <math.h>

#define NN 100000
#define EE 1600000
#define F_IN 1433
#define DD 64
#define DEPTH 3
#define ALPHA 0.9f
#define KC_EMB 90   // ceil(1433/16)

// ---------------- scratch (static device globals) ----------------
__device__ float g_x0[NN * DD];
__device__ float g_x [NN * DD];
__device__ float g_h [NN * DD];   // LN output, later reused as agg
__device__ float g_q [NN * DD];
__device__ float g_k [NN * DD];
__device__ float g_v [NN * DD];
__device__ float g_o [NN * DD];
__device__ int   g_deg[NN];
__device__ int   g_off[NN + 1];
__device__ int   g_pos[NN];
__device__ int   g_csr[EE];
__device__ uint4 g_Bemb[KC_EMB * 256];   // packed split-bf16 emb weight
__device__ uint4 g_Bw[12 * 1024];        // q,k,v,o x 3 layers (K=64 -> KC=4)

// ---------------- helpers ----------------
__device__ __forceinline__ void split2(float x, float y, unsigned& hi, unsigned& lo) {
    __nv_bfloat162 h = __floats2bfloat162_rn(x, y);
    float rx = x - __low2float(h);
    float ry = y - __high2float(h);
    __nv_bfloat162 l = __floats2bfloat162_rn(rx, ry);
    hi = *reinterpret_cast<unsigned*>(&h);
    lo = *reinterpret_cast<unsigned*>(&l);
}

__device__ __forceinline__ void mma16816(float* c, const unsigned* a,
                                         unsigned b0, unsigned b1) {
    asm volatile(
        "mma.sync.aligned.m16n8k16.row.col.f32.bf16.bf16.f32 "
        "{%0,%1,%2,%3},{%4,%5,%6,%7},{%8,%9},{%0,%1,%2,%3};\n"
        : "+f"(c[0]), "+f"(c[1]), "+f"(c[2]), "+f"(c[3])
        : "r"(a[0]), "r"(a[1]), "r"(a[2]), "r"(a[3]), "r"(b0), "r"(b1));
}

// ---------------- B packing ----------------
__global__ void pack_b_kernel(const float* __restrict__ B, uint4* __restrict__ out,
                              int K, int KC) {
    int idx = blockIdx.x * blockDim.x + threadIdx.x;
    if (idx >= KC * 256) return;
    int lane = idx & 31, nt = (idx >> 5) & 7, kc = idx >> 8;
    int col = nt * 8 + (lane >> 2);
    int kr = kc * 16 + (lane & 3) * 2;
    float f0 = (kr     < K) ? B[(kr    ) * 64 + col] : 0.f;
    float f1 = (kr + 1 < K) ? B[(kr + 1) * 64 + col] : 0.f;
    float f2 = (kr + 8 < K) ? B[(kr + 8) * 64 + col] : 0.f;
    float f3 = (kr + 9 < K) ? B[(kr + 9) * 64 + col] : 0.f;
    unsigned h0, l0, h1, l1;
    split2(f0, f1, h0, l0);
    split2(f2, f3, h1, l1);
    out[idx] = make_uint4(h0, h1, l0, l1);
}

__global__ void pack_w_kernel(const float* __restrict__ Wq, const float* __restrict__ Wk,
                              const float* __restrict__ Wv, const float* __restrict__ Wo,
                              uint4* __restrict__ out) {
    int idx = blockIdx.x * blockDim.x + threadIdx.x;
    if (idx >= 12 * 1024) return;
    int m = idx >> 10;
    int l = m >> 2, w = m & 3;
    const float* B = (w == 0 ? Wq : w == 1 ? Wk : w == 2 ? Wv : Wo) + l * 4096;
    int rest = idx & 1023;
    int lane = rest & 31, nt = (rest >> 5) & 7, kc = rest >> 8;
    int col = nt * 8 + (lane >> 2);
    int kr = kc * 16 + (lane & 3) * 2;
    float f0 = B[(kr    ) * 64 + col];
    float f1 = B[(kr + 1) * 64 + col];
    float f2 = B[(kr + 8) * 64 + col];
    float f3 = B[(kr + 9) * 64 + col];
    unsigned h0, l0, h1, l1;
    split2(f0, f1, h0, l0);
    split2(f2, f3, h1, l1);
    out[idx] = make_uint4(h0, h1, l0, l1);
}

// ---------------- smem-staged split-bf16 tensor-core GEMM ----------------
// C[m][M x 64] = A[M x K] @ B_m[K x 64]; 64 rows per block, 128 threads.
// A slab (64 rows x 32 cols) staged in smem via coalesced loads; consumers
// read fragments as conflict-free LDS.64 (XOR swizzle on bits 3..4 of col).
template <int NB>
__global__ __launch_bounds__(128)
void gemm_smem_kernel(const float* __restrict__ A, const uint4* __restrict__ Bp,
                      float* __restrict__ O0, float* __restrict__ O1,
                      float* __restrict__ O2,
                      const float* __restrict__ bias, int M, int K, int KC) {
    __shared__ float sA[64 * 32];
    const int tid = threadIdx.x, warp = tid >> 5, lane = tid & 31;
    const int rowBase = blockIdx.x * 64;

    float acc[NB][8][4];
#pragma unroll
    for (int m = 0; m < NB; ++m)
#pragma unroll
        for (int nt = 0; nt < 8; ++nt)
#pragma unroll
            for (int j = 0; j < 4; ++j) acc[m][nt][j] = 0.f;

    // consumer fragment rows within the block tile
    const int cr0 = warp * 16 + (lane >> 2);       // 0..63
    const int cr1 = cr0 + 8;
    const int sw0 = (cr0 & 3) << 3;
    const int sw1 = (cr1 & 3) << 3;

    const int nStages = (KC + 1) >> 1;
    for (int st = 0; st < nStages; ++st) {
        const int cBase = st * 32;
        // -------- producer: warp w fills rows w, w+4, ... (16 rows) --------
#pragma unroll 4
        for (int rr = warp; rr < 64; rr += 4) {
            int gr = rowBase + rr;
            int gc = cBase + lane;
            float v = (gr < M && gc < K) ? __ldg(A + (long)gr * K + gc) : 0.f;
            sA[rr * 32 + (lane ^ ((rr & 3) << 3))] = v;
        }
        __syncthreads();
        // -------- consume the two 16-col chunks --------
#pragma unroll
        for (int half = 0; half < 2; ++half) {
            int kc = st * 2 + half;
            if (kc < KC) {
                int c0 = half * 16 + (lane & 3) * 2;
                float2 fA = *(const float2*)&sA[cr0 * 32 + ((c0    ) ^ sw0)];
                float2 fB = *(const float2*)&sA[cr1 * 32 + ((c0    ) ^ sw1)];
                float2 fC = *(const float2*)&sA[cr0 * 32 + ((c0 + 8) ^ sw0)];
                float2 fD = *(const float2*)&sA[cr1 * 32 + ((c0 + 8) ^ sw1)];
                unsigned ahi[4], alo[4];
                split2(fA.x, fA.y, ahi[0], alo[0]);
                split2(fB.x, fB.y, ahi[1], alo[1]);
                split2(fC.x, fC.y, ahi[2], alo[2]);
                split2(fD.x, fD.y, ahi[3], alo[3]);
                const uint4* bp = Bp + (size_t)kc * 256 + lane;
#pragma unroll
                for (int m = 0; m < NB; ++m) {
                    const uint4* bm = bp + (size_t)m * KC * 256;
#pragma unroll
                    for (int nt = 0; nt < 8; ++nt) {
                        uint4 b = __ldg(&bm[nt * 32]);
                        mma16816(acc[m][nt], ahi, b.x, b.y);  // hi*hi
                        mma16816(acc[m][nt], alo, b.x, b.y);  // lo*hi
                        mma16816(acc[m][nt], ahi, b.z, b.w);  // hi*lo
                    }
                }
            }
        }
        __syncthreads();
    }

    const int gr0 = rowBase + cr0;
    const int gr1 = rowBase + cr1;
    float* outs[3];
    outs[0] = O0; outs[1] = O1; outs[2] = O2;
#pragma unroll
    for (int m = 0; m < NB; ++m) {
        float* O = outs[m];
#pragma unroll
        for (int nt = 0; nt < 8; ++nt) {
            int cc = nt * 8 + (lane & 3) * 2;
            float b0 = bias ? bias[cc] : 0.f;
            float b1 = bias ? bias[cc + 1] : 0.f;
            if (gr0 < M)
                *(float2*)(O + (long)gr0 * 64 + cc) =
                    make_float2(acc[m][nt][0] + b0, acc[m][nt][1] + b1);
            if (gr1 < M)
                *(float2*)(O + (long)gr1 * 64 + cc) =
                    make_float2(acc[m][nt][2] + b0, acc[m][nt][3] + b1);
        }
    }
}

// ---------------- CSR construction ----------------
__global__ void zero_deg_kernel() {
    int i = blockIdx.x * blockDim.x + threadIdx.x;
    if (i < NN) g_deg[i] = 0;
}

__global__ void hist_kernel(const int* __restrict__ ei) {
    int e = blockIdx.x * blockDim.x + threadIdx.x;
    if (e < EE) atomicAdd(&g_deg[ei[EE + e]], 1);
}

__global__ void scan_kernel() {
    __shared__ int ssum[1024];
    const int t = threadIdx.x;
    const int CHUNK = (NN + 1023) / 1024;
    int beg = t * CHUNK;
    int end = beg + CHUNK; if (end > NN) end = NN;
    int s = 0;
    for (int i = beg; i < end; ++i) s += g_deg[i];
    ssum[t] = s;
    __syncthreads();
    for (int d = 1; d < 1024; d <<= 1) {
        int v = (t >= d) ? ssum[t - d] : 0;
        __syncthreads();
        ssum[t] += v;
        __syncthreads();
    }
    int run = (t == 0) ? 0 : ssum[t - 1];
    for (int i = beg; i < end; ++i) {
        g_off[i] = run;
        g_pos[i] = run;
        run += g_deg[i];
    }
    if (t == 1023) g_off[NN] = ssum[1023];
}

__global__ void fill_kernel(const int* __restrict__ ei) {
    int e = blockIdx.x * blockDim.x + threadIdx.x;
    if (e < EE) {
        int d = ei[EE + e];
        int p = atomicAdd(&g_pos[d], 1);
        g_csr[p] = ei[e];
    }
}

// ---------------- layer norm (standalone, layer 0 only) ----------------
__global__ void ln_kernel(const float* __restrict__ src,
                          const float* __restrict__ scale,
                          const float* __restrict__ bias) {
    int warp = (blockIdx.x * blockDim.x + threadIdx.x) >> 5;
    int lane = threadIdx.x & 31;
    if (warp >= NN) return;
    const float* xr = src + (size_t)warp * 64;
    float x0v = xr[lane], x1v = xr[lane + 32];
    float s = x0v + x1v;
    float sq = x0v * x0v + x1v * x1v;
#pragma unroll
    for (int o = 16; o; o >>= 1) {
        s  += __shfl_xor_sync(~0u, s,  o);
        sq += __shfl_xor_sync(~0u, sq, o);
    }
    float mu = s * (1.f / 64.f);
    float var = sq * (1.f / 64.f) - mu * mu;
    float rstd = rsqrtf(var + 1e-5f);
    float* hr = g_h + (size_t)warp * 64;
    hr[lane]      = (x0v - mu) * rstd * scale[lane]      + bias[lane];
    hr[lane + 32] = (x1v - mu) * rstd * scale[lane + 32] + bias[lane + 32];
}

// ---------------- fused edge attention: warp per dst, float2 lanes ---------
// lane j owns dims (2j, 2j+1); head = j>>3; dot reduced over 8-lane groups.
__global__ __launch_bounds__(256)
void attn_kernel() {
    int warp = (blockIdx.x * blockDim.x + threadIdx.x) >> 5;
    int lane = threadIdx.x & 31;
    if (warp >= NN) return;
    float2 qv = ((const float2*)(g_q + (size_t)warp * 64))[lane];
    qv.x *= 0.25f; qv.y *= 0.25f;      // fold DH^-0.5
    float l = 0.f, lB = 0.f;
    float ax = 0.f, ay = 0.f, bx = 0.f, by = 0.f;
    int beg = g_off[warp], end = g_off[warp + 1];
    int e = beg;
    for (; e + 1 < end; e += 2) {
        int s0 = g_csr[e], s1 = g_csr[e + 1];
        float2 k0 = ((const float2*)(g_k + (size_t)s0 * 64))[lane];
        float2 v0 = ((const float2*)(g_v + (size_t)s0 * 64))[lane];
        float2 k1 = ((const float2*)(g_k + (size_t)s1 * 64))[lane];
        float2 v1 = ((const float2*)(g_v + (size_t)s1 * 64))[lane];
        float d0 = qv.x * k0.x + qv.y * k0.y;
        float d1 = qv.x * k1.x + qv.y * k1.y;
#pragma unroll
        for (int o = 4; o; o >>= 1) {
            d0 += __shfl_xor_sync(~0u, d0, o);
            d1 += __shfl_xor_sync(~0u, d1, o);
        }
        float p0 = __expf(d0), p1 = __expf(d1);
        l  += p0;  ax += p0 * v0.x;  ay += p0 * v0.y;
        lB += p1;  bx += p1 * v1.x;  by += p1 * v1.y;
    }
    if (e < end) {
        int s0 = g_csr[e];
        float2 k0 = ((const float2*)(g_k + (size_t)s0 * 64))[lane];
        float2 v0 = ((const float2*)(g_v + (size_t)s0 * 64))[lane];
        float d0 = qv.x * k0.x + qv.y * k0.y;
#pragma unroll
        for (int o = 4; o; o >>= 1) d0 += __shfl_xor_sync(~0u, d0, o);
        float p0 = __expf(d0);
        l += p0; ax += p0 * v0.x; ay += p0 * v0.y;
    }
    l += lB; ax += bx; ay += by;
    float inv = 1.f / (l + 1e-9f);
    ((float2*)(g_h + (size_t)warp * 64))[lane] = make_float2(ax * inv, ay * inv);
}

// ---------------- gated residual + alpha mix (+ fused next-layer LN) -------
__global__ void gate_kernel(const float* __restrict__ gw,
                            const float* __restrict__ gbp,
                            const float* __restrict__ res,
                            const float* __restrict__ x0,
                            float* __restrict__ dst,
                            const float* __restrict__ lns,
                            const float* __restrict__ lnb) {
    int warp = (blockIdx.x * blockDim.x + threadIdx.x) >> 5;
    int lane = threadIdx.x & 31;
    if (warp >= NN) return;
    size_t base = (size_t)warp * 64;
    float o0 = g_o[base + lane], o1 = g_o[base + lane + 32];
    float r0 = res[base + lane], r1 = res[base + lane + 32];
    float z0 = x0[base + lane],  z1 = x0[base + lane + 32];
    float s = o0 * gw[lane]        + o1 * gw[lane + 32]
            + r0 * gw[64 + lane]   + r1 * gw[96 + lane]
            + (o0 - r0) * gw[128 + lane] + (o1 - r1) * gw[160 + lane];
#pragma unroll
    for (int o = 16; o; o >>= 1) s += __shfl_xor_sync(~0u, s, o);
    float g = 1.f / (1.f + __expf(-(s + gbp[0])));
    float n0 = ALPHA * (g * o0 + (1.f - g) * r0) + (1.f - ALPHA) * z0;
    float n1 = ALPHA * (g * o1 + (1.f - g) * r1) + (1.f - ALPHA) * z1;
    dst[base + lane]      = n0;
    dst[base + lane + 32] = n1;
    if (lns) {  // fused LN for next layer -> g_h
        float sm = n0 + n1, sq = n0 * n0 + n1 * n1;
#pragma unroll
        for (int o = 16; o; o >>= 1) {
            sm += __shfl_xor_sync(~0u, sm, o);
            sq += __shfl_xor_sync(~0u, sq, o);
        }
        float mu = sm * (1.f / 64.f);
        float var = sq * (1.f / 64.f) - mu * mu;
        float rstd = rsqrtf(var + 1e-5f);
        g_h[base + lane]      = (n0 - mu) * rstd * lns[lane]      + lnb[lane];
        g_h[base + lane + 32] = (n1 - mu) * rstd * lns[lane + 32] + lnb[lane + 32];
    }
}

// ---------------- launch ----------------
extern "C" void kernel_launch(void* const* d_in, const int* in_sizes, int n_in,
                              void* d_out, int out_size) {
    const float* nodes = (const float*)d_in[0];
    const int*   ei    = (const int*)  d_in[1];
    const float* emb_W = (const float*)d_in[2];
    const float* emb_b = (const float*)d_in[3];
    const float* ln_s  = (const float*)d_in[4];
    const float* ln_b  = (const float*)d_in[5];
    const float* Wq    = (const float*)d_in[6];
    const float* Wk    = (const float*)d_in[7];
    const float* Wv    = (const float*)d_in[8];
    const float* Wo    = (const float*)d_in[9];
    const float* gW    = (const float*)d_in[10];
    const float* gb    = (const float*)d_in[11];
    float* out = (float*)d_out;

    float *px0, *px, *ph, *pq, *pk, *pv, *po;
    uint4 *pBemb, *pBw;
    cudaGetSymbolAddress((void**)&px0, g_x0);
    cudaGetSymbolAddress((void**)&px,  g_x);
    cudaGetSymbolAddress((void**)&ph,  g_h);
    cudaGetSymbolAddress((void**)&pq,  g_q);
    cudaGetSymbolAddress((void**)&pk,  g_k);
    cudaGetSymbolAddress((void**)&pv,  g_v);
    cudaGetSymbolAddress((void**)&po,  g_o);
    cudaGetSymbolAddress((void**)&pBemb, g_Bemb);
    cudaGetSymbolAddress((void**)&pBw,   g_Bw);

    const int gemmGrid = (NN + 63) / 64;   // 1563
    const int warpGrid = (NN + 7) / 8;

    // launches 1-3
    pack_b_kernel<<<(KC_EMB * 256 + 255) / 256, 256>>>(emb_W, pBemb, F_IN, KC_EMB);
    pack_w_kernel<<<(12 * 1024 + 255) / 256, 256>>>(Wq, Wk, Wv, Wo, pBw);
    zero_deg_kernel<<<(NN + 255) / 256, 256>>>();
    // launch 4: the one ncu captures -> embedding GEMM
    gemm_smem_kernel<1><<<gemmGrid, 128>>>(nodes, pBemb, px0, nullptr, nullptr,
                                           emb_b, NN, F_IN, KC_EMB);
    // CSR build
    hist_kernel<<<(EE + 255) / 256, 256>>>(ei);
    scan_kernel<<<1, 1024>>>();
    fill_kernel<<<(EE + 255) / 256, 256>>>(ei);

    // layer 0 LN reads x0 directly (x == x0 initially)
    ln_kernel<<<warpGrid, 256>>>(px0, ln_s, ln_b);
    for (int l = 0; l < DEPTH; ++l) {
        gemm_smem_kernel<3><<<gemmGrid, 128>>>(
            ph, pBw + (size_t)(l * 4) * 1024, pq, pk, pv, nullptr, NN, 64, 4);
        attn_kernel<<<warpGrid, 256>>>();   // agg -> g_h
        gemm_smem_kernel<1><<<gemmGrid, 128>>>(
            ph, pBw + (size_t)(l * 4 + 3) * 1024, po, nullptr, nullptr,
            nullptr, NN, 64, 4);
        const float* res = (l == 0) ? px0 : px;
        float* dst = (l == DEPTH - 1) ? out : px;
        const float* nls = (l == DEPTH - 1) ? nullptr : ln_s + (l + 1) * 64;
        const float* nlb = (l == DEPTH - 1) ? nullptr : ln_b + (l + 1) * 64;
        gate_kernel<<<warpGrid, 256>>>(gW + l * 192, gb + l, res, px0, dst,
                                       nls, nlb);
    }
}

// round 6
// speedup vs baseline: 1.3389x; 1.1699x over previous
#include <cuda_runtime.h>
#include <cuda_bf16.h>
#include <math.h>

#define NN 100000
#define EE 1600000
#define F_IN 1433
#define DD 64
#define DEPTH 3
#define ALPHA 0.9f
#define KC_EMB 90   // ceil(1433/16)

// ---------------- scratch (static device globals) ----------------
__device__ float g_x0[NN * DD];
__device__ float g_x [NN * DD];
__device__ float g_h [NN * DD];   // LN output, later reused as agg
__device__ float g_q [NN * DD];
__device__ float g_k [NN * DD];
__device__ float g_v [NN * DD];
__device__ float g_o [NN * DD];
__device__ int   g_deg[NN];
__device__ int   g_off[NN + 1];
__device__ int   g_pos[NN];
__device__ int   g_csr[EE];
__device__ uint4 g_Bemb[KC_EMB * 256];   // packed split-bf16 emb weight
__device__ uint4 g_Bw[12 * 1024];        // q,k,v,o x 3 layers (K=64 -> KC=4)

// ---------------- helpers ----------------
__device__ __forceinline__ void split2(float x, float y, unsigned& hi, unsigned& lo) {
    __nv_bfloat162 h = __floats2bfloat162_rn(x, y);
    float rx = x - __low2float(h);
    float ry = y - __high2float(h);
    __nv_bfloat162 l = __floats2bfloat162_rn(rx, ry);
    hi = *reinterpret_cast<unsigned*>(&h);
    lo = *reinterpret_cast<unsigned*>(&l);
}

__device__ __forceinline__ void mma16816(float* c, const unsigned* a,
                                         unsigned b0, unsigned b1) {
    asm volatile(
        "mma.sync.aligned.m16n8k16.row.col.f32.bf16.bf16.f32 "
        "{%0,%1,%2,%3},{%4,%5,%6,%7},{%8,%9},{%0,%1,%2,%3};\n"
        : "+f"(c[0]), "+f"(c[1]), "+f"(c[2]), "+f"(c[3])
        : "r"(a[0]), "r"(a[1]), "r"(a[2]), "r"(a[3]), "r"(b0), "r"(b1));
}

// ---------------- B packing ----------------
__global__ void pack_b_kernel(const float* __restrict__ B, uint4* __restrict__ out,
                              int K, int KC) {
    int idx = blockIdx.x * blockDim.x + threadIdx.x;
    if (idx >= KC * 256) return;
    int lane = idx & 31, nt = (idx >> 5) & 7, kc = idx >> 8;
    int col = nt * 8 + (lane >> 2);
    int kr = kc * 16 + (lane & 3) * 2;
    float f0 = (kr     < K) ? B[(kr    ) * 64 + col] : 0.f;
    float f1 = (kr + 1 < K) ? B[(kr + 1) * 64 + col] : 0.f;
    float f2 = (kr + 8 < K) ? B[(kr + 8) * 64 + col] : 0.f;
    float f3 = (kr + 9 < K) ? B[(kr + 9) * 64 + col] : 0.f;
    unsigned h0, l0, h1, l1;
    split2(f0, f1, h0, l0);
    split2(f2, f3, h1, l1);
    out[idx] = make_uint4(h0, h1, l0, l1);
}

__global__ void pack_w_kernel(const float* __restrict__ Wq, const float* __restrict__ Wk,
                              const float* __restrict__ Wv, const float* __restrict__ Wo,
                              uint4* __restrict__ out) {
    int idx = blockIdx.x * blockDim.x + threadIdx.x;
    if (idx >= 12 * 1024) return;
    int m = idx >> 10;
    int l = m >> 2, w = m & 3;
    const float* B = (w == 0 ? Wq : w == 1 ? Wk : w == 2 ? Wv : Wo) + l * 4096;
    int rest = idx & 1023;
    int lane = rest & 31, nt = (rest >> 5) & 7, kc = rest >> 8;
    int col = nt * 8 + (lane >> 2);
    int kr = kc * 16 + (lane & 3) * 2;
    float f0 = B[(kr    ) * 64 + col];
    float f1 = B[(kr + 1) * 64 + col];
    float f2 = B[(kr + 8) * 64 + col];
    float f3 = B[(kr + 9) * 64 + col];
    unsigned h0, l0, h1, l1;
    split2(f0, f1, h0, l0);
    split2(f2, f3, h1, l1);
    out[idx] = make_uint4(h0, h1, l0, l1);
}

// ------- register-staged pipelined split-bf16 tensor-core GEMM -------------
// C[m][M x 64] = A[M x K] @ B_m[K x 64]; 64 rows/block, 128 threads.
// Stage st+1's A slab is LDG'd into registers while stage st's MMAs run.
template <int NB>
__global__ __launch_bounds__(128)
void gemm_pipe_kernel(const float* __restrict__ A, const uint4* __restrict__ Bp,
                      float* __restrict__ O0, float* __restrict__ O1,
                      float* __restrict__ O2,
                      const float* __restrict__ bias, int M, int K, int KC) {
    __shared__ float sA[64 * 32];
    const int tid = threadIdx.x, warp = tid >> 5, lane = tid & 31;
    const int rowBase = blockIdx.x * 64;
    const int nStages = (KC + 1) >> 1;

    float acc[NB][8][4];
#pragma unroll
    for (int m = 0; m < NB; ++m)
#pragma unroll
        for (int nt = 0; nt < 8; ++nt)
#pragma unroll
            for (int j = 0; j < 4; ++j) acc[m][nt][j] = 0.f;

    // consumer fragment rows
    const int cr0 = warp * 16 + (lane >> 2);
    const int cr1 = cr0 + 8;
    const int sw0 = (cr0 & 3) << 3;
    const int sw1 = (cr1 & 3) << 3;

    // producer: thread covers rows {warp, warp+4, ..., warp+60}, col = lane
    float rbuf[16];

#define LOADSTAGE(ST)                                                          \
    do {                                                                       \
        int cBase = (ST) * 32;                                                 \
        int gc = cBase + lane;                                                 \
        bool cok = gc < K;                                                     \
        _Pragma("unroll")                                                      \
        for (int i = 0; i < 16; ++i) {                                         \
            int gr = rowBase + i * 4 + warp;                                   \
            rbuf[i] = (gr < M && cok) ? __ldg(A + (long)gr * K + gc) : 0.f;    \
        }                                                                      \
    } while (0)

    LOADSTAGE(0);
    for (int st = 0; st < nStages; ++st) {
        // commit staged registers to smem (swizzled)
#pragma unroll
        for (int i = 0; i < 16; ++i) {
            int rr = i * 4 + warp;
            sA[rr * 32 + (lane ^ ((rr & 3) << 3))] = rbuf[i];
        }
        __syncthreads();
        // issue next stage's LDGs now — in flight during the MMA phase
        if (st + 1 < nStages) LOADSTAGE(st + 1);
#pragma unroll
        for (int half = 0; half < 2; ++half) {
            int kc = st * 2 + half;
            if (kc < KC) {
                int c0 = half * 16 + (lane & 3) * 2;
                float2 fA = *(const float2*)&sA[cr0 * 32 + ((c0    ) ^ sw0)];
                float2 fB = *(const float2*)&sA[cr1 * 32 + ((c0    ) ^ sw1)];
                float2 fC = *(const float2*)&sA[cr0 * 32 + ((c0 + 8) ^ sw0)];
                float2 fD = *(const float2*)&sA[cr1 * 32 + ((c0 + 8) ^ sw1)];
                unsigned ahi[4], alo[4];
                split2(fA.x, fA.y, ahi[0], alo[0]);
                split2(fB.x, fB.y, ahi[1], alo[1]);
                split2(fC.x, fC.y, ahi[2], alo[2]);
                split2(fD.x, fD.y, ahi[3], alo[3]);
                const uint4* bp = Bp + (size_t)kc * 256 + lane;
#pragma unroll
                for (int m = 0; m < NB; ++m) {
                    const uint4* bm = bp + (size_t)m * KC * 256;
#pragma unroll
                    for (int nt = 0; nt < 8; ++nt) {
                        uint4 b = __ldg(&bm[nt * 32]);
                        mma16816(acc[m][nt], ahi, b.x, b.y);  // hi*hi
                        mma16816(acc[m][nt], alo, b.x, b.y);  // lo*hi
                        mma16816(acc[m][nt], ahi, b.z, b.w);  // hi*lo
                    }
                }
            }
        }
        __syncthreads();
    }
#undef LOADSTAGE

    const int gr0 = rowBase + cr0;
    const int gr1 = rowBase + cr1;
    float* outs[3];
    outs[0] = O0; outs[1] = O1; outs[2] = O2;
#pragma unroll
    for (int m = 0; m < NB; ++m) {
        float* O = outs[m];
#pragma unroll
        for (int nt = 0; nt < 8; ++nt) {
            int cc = nt * 8 + (lane & 3) * 2;
            float b0 = bias ? bias[cc] : 0.f;
            float b1 = bias ? bias[cc + 1] : 0.f;
            if (gr0 < M)
                *(float2*)(O + (long)gr0 * 64 + cc) =
                    make_float2(acc[m][nt][0] + b0, acc[m][nt][1] + b1);
            if (gr1 < M)
                *(float2*)(O + (long)gr1 * 64 + cc) =
                    make_float2(acc[m][nt][2] + b0, acc[m][nt][3] + b1);
        }
    }
}

// ---------------- CSR construction ----------------
__global__ void zero_deg_kernel() {
    int i = blockIdx.x * blockDim.x + threadIdx.x;
    if (i < NN) g_deg[i] = 0;
}

__global__ void hist_kernel(const int* __restrict__ ei) {
    int e = blockIdx.x * blockDim.x + threadIdx.x;
    if (e < EE) atomicAdd(&g_deg[ei[EE + e]], 1);
}

__global__ void scan_kernel() {
    __shared__ int ssum[1024];
    const int t = threadIdx.x;
    const int CHUNK = (NN + 1023) / 1024;
    int beg = t * CHUNK;
    int end = beg + CHUNK; if (end > NN) end = NN;
    int s = 0;
    for (int i = beg; i < end; ++i) s += g_deg[i];
    ssum[t] = s;
    __syncthreads();
    for (int d = 1; d < 1024; d <<= 1) {
        int v = (t >= d) ? ssum[t - d] : 0;
        __syncthreads();
        ssum[t] += v;
        __syncthreads();
    }
    int run = (t == 0) ? 0 : ssum[t - 1];
    for (int i = beg; i < end; ++i) {
        g_off[i] = run;
        g_pos[i] = run;
        run += g_deg[i];
    }
    if (t == 1023) g_off[NN] = ssum[1023];
}

__global__ void fill_kernel(const int* __restrict__ ei) {
    int e = blockIdx.x * blockDim.x + threadIdx.x;
    if (e < EE) {
        int d = ei[EE + e];
        int p = atomicAdd(&g_pos[d], 1);
        g_csr[p] = ei[e];
    }
}

// ---------------- layer norm (standalone, layer 0 only) ----------------
__global__ void ln_kernel(const float* __restrict__ src,
                          const float* __restrict__ scale,
                          const float* __restrict__ bias) {
    int warp = (blockIdx.x * blockDim.x + threadIdx.x) >> 5;
    int lane = threadIdx.x & 31;
    if (warp >= NN) return;
    const float* xr = src + (size_t)warp * 64;
    float x0v = xr[lane], x1v = xr[lane + 32];
    float s = x0v + x1v;
    float sq = x0v * x0v + x1v * x1v;
#pragma unroll
    for (int o = 16; o; o >>= 1) {
        s  += __shfl_xor_sync(~0u, s,  o);
        sq += __shfl_xor_sync(~0u, sq, o);
    }
    float mu = s * (1.f / 64.f);
    float var = sq * (1.f / 64.f) - mu * mu;
    float rstd = rsqrtf(var + 1e-5f);
    float* hr = g_h + (size_t)warp * 64;
    hr[lane]      = (x0v - mu) * rstd * scale[lane]      + bias[lane];
    hr[lane + 32] = (x1v - mu) * rstd * scale[lane + 32] + bias[lane + 32];
}

// ---------------- fused edge attention: warp per dst, float2 lanes ---------
__global__ __launch_bounds__(256)
void attn_kernel() {
    int warp = (blockIdx.x * blockDim.x + threadIdx.x) >> 5;
    int lane = threadIdx.x & 31;
    if (warp >= NN) return;
    float2 qv = ((const float2*)(g_q + (size_t)warp * 64))[lane];
    qv.x *= 0.25f; qv.y *= 0.25f;      // fold DH^-0.5
    float l = 0.f, lB = 0.f;
    float ax = 0.f, ay = 0.f, bx = 0.f, by = 0.f;
    int beg = g_off[warp], end = g_off[warp + 1];
    int e = beg;
    for (; e + 1 < end; e += 2) {
        int s0 = g_csr[e], s1 = g_csr[e + 1];
        float2 k0 = ((const float2*)(g_k + (size_t)s0 * 64))[lane];
        float2 v0 = ((const float2*)(g_v + (size_t)s0 * 64))[lane];
        float2 k1 = ((const float2*)(g_k + (size_t)s1 * 64))[lane];
        float2 v1 = ((const float2*)(g_v + (size_t)s1 * 64))[lane];
        float d0 = qv.x * k0.x + qv.y * k0.y;
        float d1 = qv.x * k1.x + qv.y * k1.y;
#pragma unroll
        for (int o = 4; o; o >>= 1) {
            d0 += __shfl_xor_sync(~0u, d0, o);
            d1 += __shfl_xor_sync(~0u, d1, o);
        }
        float p0 = __expf(d0), p1 = __expf(d1);
        l  += p0;  ax += p0 * v0.x;  ay += p0 * v0.y;
        lB += p1;  bx += p1 * v1.x;  by += p1 * v1.y;
    }
    if (e < end) {
        int s0 = g_csr[e];
        float2 k0 = ((const float2*)(g_k + (size_t)s0 * 64))[lane];
        float2 v0 = ((const float2*)(g_v + (size_t)s0 * 64))[lane];
        float d0 = qv.x * k0.x + qv.y * k0.y;
#pragma unroll
        for (int o = 4; o; o >>= 1) d0 += __shfl_xor_sync(~0u, d0, o);
        float p0 = __expf(d0);
        l += p0; ax += p0 * v0.x; ay += p0 * v0.y;
    }
    l += lB; ax += bx; ay += by;
    float inv = 1.f / (l + 1e-9f);
    ((float2*)(g_h + (size_t)warp * 64))[lane] = make_float2(ax * inv, ay * inv);
}

// ---------------- gated residual + alpha mix (+ fused next-layer LN) -------
__global__ void gate_kernel(const float* __restrict__ gw,
                            const float* __restrict__ gbp,
                            const float* __restrict__ res,
                            const float* __restrict__ x0,
                            float* __restrict__ dst,
                            const float* __restrict__ lns,
                            const float* __restrict__ lnb) {
    int warp = (blockIdx.x * blockDim.x + threadIdx.x) >> 5;
    int lane = threadIdx.x & 31;
    if (warp >= NN) return;
    size_t base = (size_t)warp * 64;
    float o0 = g_o[base + lane], o1 = g_o[base + lane + 32];
    float r0 = res[base + lane], r1 = res[base + lane + 32];
    float z0 = x0[base + lane],  z1 = x0[base + lane + 32];
    float s = o0 * gw[lane]        + o1 * gw[lane + 32]
            + r0 * gw[64 + lane]   + r1 * gw[96 + lane]
            + (o0 - r0) * gw[128 + lane] + (o1 - r1) * gw[160 + lane];
#pragma unroll
    for (int o = 16; o; o >>= 1) s += __shfl_xor_sync(~0u, s, o);
    float g = 1.f / (1.f + __expf(-(s + gbp[0])));
    float n0 = ALPHA * (g * o0 + (1.f - g) * r0) + (1.f - ALPHA) * z0;
    float n1 = ALPHA * (g * o1 + (1.f - g) * r1) + (1.f - ALPHA) * z1;
    dst[base + lane]      = n0;
    dst[base + lane + 32] = n1;
    if (lns) {  // fused LN for next layer -> g_h
        float sm = n0 + n1, sq = n0 * n0 + n1 * n1;
#pragma unroll
        for (int o = 16; o; o >>= 1) {
            sm += __shfl_xor_sync(~0u, sm, o);
            sq += __shfl_xor_sync(~0u, sq, o);
        }
        float mu = sm * (1.f / 64.f);
        float var = sq * (1.f / 64.f) - mu * mu;
        float rstd = rsqrtf(var + 1e-5f);
        g_h[base + lane]      = (n0 - mu) * rstd * lns[lane]      + lnb[lane];
        g_h[base + lane + 32] = (n1 - mu) * rstd * lns[lane + 32] + lnb[lane + 32];
    }
}

// ---------------- launch ----------------
extern "C" void kernel_launch(void* const* d_in, const int* in_sizes, int n_in,
                              void* d_out, int out_size) {
    const float* nodes = (const float*)d_in[0];
    const int*   ei    = (const int*)  d_in[1];
    const float* emb_W = (const float*)d_in[2];
    const float* emb_b = (const float*)d_in[3];
    const float* ln_s  = (const float*)d_in[4];
    const float* ln_b  = (const float*)d_in[5];
    const float* Wq    = (const float*)d_in[6];
    const float* Wk    = (const float*)d_in[7];
    const float* Wv    = (const float*)d_in[8];
    const float* Wo    = (const float*)d_in[9];
    const float* gW    = (const float*)d_in[10];
    const float* gb    = (const float*)d_in[11];
    float* out = (float*)d_out;

    float *px0, *px, *ph, *pq, *pk, *pv, *po;
    uint4 *pBemb, *pBw;
    cudaGetSymbolAddress((void**)&px0, g_x0);
    cudaGetSymbolAddress((void**)&px,  g_x);
    cudaGetSymbolAddress((void**)&ph,  g_h);
    cudaGetSymbolAddress((void**)&pq,  g_q);
    cudaGetSymbolAddress((void**)&pk,  g_k);
    cudaGetSymbolAddress((void**)&pv,  g_v);
    cudaGetSymbolAddress((void**)&po,  g_o);
    cudaGetSymbolAddress((void**)&pBemb, g_Bemb);
    cudaGetSymbolAddress((void**)&pBw,   g_Bw);

    const int gemmGrid = (NN + 63) / 64;   // 1563
    const int warpGrid = (NN + 7) / 8;

    // launches 1-3
    pack_b_kernel<<<(KC_EMB * 256 + 255) / 256, 256>>>(emb_W, pBemb, F_IN, KC_EMB);
    pack_w_kernel<<<(12 * 1024 + 255) / 256, 256>>>(Wq, Wk, Wv, Wo, pBw);
    zero_deg_kernel<<<(NN + 255) / 256, 256>>>();
    // launch 4: the one ncu captures -> embedding GEMM
    gemm_pipe_kernel<1><<<gemmGrid, 128>>>(nodes, pBemb, px0, nullptr, nullptr,
                                           emb_b, NN, F_IN, KC_EMB);
    // CSR build
    hist_kernel<<<(EE + 255) / 256, 256>>>(ei);
    scan_kernel<<<1, 1024>>>();
    fill_kernel<<<(EE + 255) / 256, 256>>>(ei);

    // layer 0 LN reads x0 directly (x == x0 initially)
    ln_kernel<<<warpGrid, 256>>>(px0, ln_s, ln_b);
    for (int l = 0; l < DEPTH; ++l) {
        gemm_pipe_kernel<3><<<gemmGrid, 128>>>(
            ph, pBw + (size_t)(l * 4) * 1024, pq, pk, pv, nullptr, NN, 64, 4);
        attn_kernel<<<warpGrid, 256>>>();   // agg -> g_h
        gemm_pipe_kernel<1><<<gemmGrid, 128>>>(
            ph, pBw + (size_t)(l * 4 + 3) * 1024, po, nullptr, nullptr,
            nullptr, NN, 64, 4);
        const float* res = (l == 0) ? px0 : px;
        float* dst = (l == DEPTH - 1) ? out : px;
        const float* nls = (l == DEPTH - 1) ? nullptr : ln_s + (l + 1) * 64;
        const float* nlb = (l == DEPTH - 1) ? nullptr : ln_b + (l + 1) * 64;
        gate_kernel<<<warpGrid, 256>>>(gW + l * 192, gb + l, res, px0, dst,
                                       nls, nlb);
    }
}